// round 4
// baseline (speedup 1.0000x reference)
#include <cuda_runtime.h>
#include <cstdint>

#define T_STEPS 1024
#define B_SZ    64
#define H_SZ    512
#define IN_SZ   512
#define G4      2048
#define NCTA    128

#define WS_STRIDE 20    // ws[k][16] padded: k-slice lanes hit disjoint banks
#define HS_STRIDE 72    // hs[k][64] padded: 72 mod 32 = 8 -> perfect 2-phase h loads

// ---------------- scratch ----------------
__device__ float    g_xpT[(size_t)T_STEPS * G4 * B_SZ];   // [t][g][b]  512 MB
__device__ float    g_hT [(size_t)T_STEPS * H_SZ * B_SZ]; // [t][j][b]  128 MB (k-major h)
__device__ unsigned g_arrive[NCTA];                       // per-CTA barrier flags

// ---------------- helpers ----------------
__device__ __forceinline__ float sigf(float x) { return 1.0f / (1.0f + __expf(-x)); }
__device__ __forceinline__ float tanh_fast(float x) {
    float ax = fabsf(x);
    float e  = __expf(-2.0f * ax);
    float t  = (1.0f - e) / (1.0f + e);
    return copysignf(t, x);
}
__device__ __forceinline__ unsigned smem_u32(const void* p) {
    return (unsigned)__cvta_generic_to_shared(p);
}
__device__ __forceinline__ void cp_async16(unsigned dst, const void* src) {
    asm volatile("cp.async.ca.shared.global [%0], [%1], 16;" :: "r"(dst), "l"(src));
}
__device__ __forceinline__ void cp_commit() {
    asm volatile("cp.async.commit_group;" ::: "memory");
}
__device__ __forceinline__ void cp_wait1() {
    asm volatile("cp.async.wait_group 1;" ::: "memory");
}
__device__ __forceinline__ void cp_wait0() {
    asm volatile("cp.async.wait_group 0;" ::: "memory");
}

// packed fp32x2 ops (Blackwell FFMA2 -- PTX only, ptxas never auto-fuses)
__device__ __forceinline__ void fma2(unsigned long long& d,
                                     unsigned long long a, unsigned long long b) {
    asm("fma.rn.f32x2 %0, %1, %2, %0;" : "+l"(d) : "l"(a), "l"(b));
}
__device__ __forceinline__ unsigned long long pack2(float x, float y) {
    unsigned long long r;
    asm("mov.b64 %0, {%1, %2};" : "=l"(r) : "f"(x), "f"(y));
    return r;
}
__device__ __forceinline__ float2 unpack2(unsigned long long v) {
    float2 f;
    asm("mov.b64 {%0, %1}, %2;" : "=f"(f.x), "=f"(f.y) : "l"(v));
    return f;
}
__device__ __forceinline__ void lds_v2u64(unsigned long long& a, unsigned long long& b,
                                          unsigned addr) {
    asm volatile("ld.shared.v2.u64 {%0, %1}, [%2];" : "=l"(a), "=l"(b) : "r"(addr));
}
__device__ __forceinline__ void lds_v2f32(float& a, float& b, unsigned addr) {
    asm volatile("ld.shared.v2.f32 {%0, %1}, [%2];" : "=f"(a), "=f"(b) : "r"(addr));
}
__device__ __forceinline__ void sts_f32(unsigned addr, float a) {
    asm volatile("st.shared.f32 [%0], %1;" :: "r"(addr), "f"(a));
}

// Grid barrier: distributed flags, release store + parallel acquire polls.
// Monotonic across launches: each CTA reads its own flag at kernel start as base.
__device__ __forceinline__ void grid_barrier(int ct, int tid, unsigned target) {
    __syncthreads();
    if (tid == 0) {
        __threadfence();  // make this CTA's global writes visible gpu-wide
        asm volatile("st.release.gpu.global.u32 [%0], %1;"
                     :: "l"(&g_arrive[ct]), "r"(target) : "memory");
    }
    if (tid < NCTA) {
        unsigned v;
        do {
            asm volatile("ld.acquire.gpu.global.u32 %0, [%1];"
                         : "=r"(v) : "l"(&g_arrive[tid]) : "memory");
        } while ((int)(v - target) < 0);
    }
    __syncthreads();
}

// =====================================================================
// Phase 1: xpT[t][g][b] = sum_k x[t,b,k] * Wx[g,k] + (bx[g] + bh[g])
// M = T*B = 65536 (rows), N = 2048 gates, K = 512.  fp32x2 SIMT GEMM.
// =====================================================================
__global__ __launch_bounds__(256) void xp_gemm(
    const float* __restrict__ x,
    const float* __restrict__ Wx0, const float* __restrict__ Wx1,
    const float* __restrict__ Wx2, const float* __restrict__ Wx3,
    const float* __restrict__ bx0, const float* __restrict__ bx1,
    const float* __restrict__ bx2, const float* __restrict__ bx3,
    const float* __restrict__ bh0, const float* __restrict__ bh1,
    const float* __restrict__ bh2, const float* __restrict__ bh3)
{
    const int BM = 128, BN = 64, BK = 16;
    __shared__ __align__(16) float As[BK][BM];
    __shared__ __align__(16) float Bs[BK][BN];

    const int bxi = blockIdx.x;          // n-tile: 0..31
    const int byi = blockIdx.y;          // m-tile: 0..511
    const int tid = threadIdx.x;

    const int gate = bxi >> 3;
    const int gin0 = (bxi & 7) * BN;
    const float* W   = (gate == 0) ? Wx0 : (gate == 1) ? Wx1 : (gate == 2) ? Wx2 : Wx3;
    const float* bxp = (gate == 0) ? bx0 : (gate == 1) ? bx1 : (gate == 2) ? bx2 : bx3;
    const float* bhp = (gate == 0) ? bh0 : (gate == 1) ? bh1 : (gate == 2) ? bh2 : bh3;

    const int row0 = byi * BM;
    const int tm   = tid & 15;
    const int tn   = tid >> 4;

    const unsigned as_base = smem_u32(&As[0][0]);

    unsigned long long ap[4][4];   // m-pairs x 4 n
    #pragma unroll
    for (int i = 0; i < 4; i++)
        #pragma unroll
        for (int j = 0; j < 4; j++) ap[i][j] = 0ull;

    for (int kk = 0; kk < IN_SZ; kk += BK) {
        #pragma unroll
        for (int it = 0; it < 2; it++) {
            int idx = tid + it * 256;
            int m = idx >> 2, k4 = idx & 3;
            float4 a = *(const float4*)&x[(size_t)(row0 + m) * IN_SZ + kk + k4 * 4];
            As[k4 * 4 + 0][m] = a.x; As[k4 * 4 + 1][m] = a.y;
            As[k4 * 4 + 2][m] = a.z; As[k4 * 4 + 3][m] = a.w;
        }
        {
            int n = tid >> 2, k4 = tid & 3;
            float4 b = *(const float4*)&W[(size_t)(gin0 + n) * IN_SZ + kk + k4 * 4];
            Bs[k4 * 4 + 0][n] = b.x; Bs[k4 * 4 + 1][n] = b.y;
            Bs[k4 * 4 + 2][n] = b.z; Bs[k4 * 4 + 3][n] = b.w;
        }
        __syncthreads();

        #pragma unroll
        for (int k = 0; k < BK; k++) {
            unsigned long long a01, a23, a45, a67;
            unsigned aaddr = as_base + (unsigned)((k * BM + tm * 8) * 4);
            lds_v2u64(a01, a23, aaddr);
            lds_v2u64(a45, a67, aaddr + 16);
            float4 bv = *(const float4*)&Bs[k][tn * 4];
            unsigned long long b0 = pack2(bv.x, bv.x);
            unsigned long long b1 = pack2(bv.y, bv.y);
            unsigned long long b2 = pack2(bv.z, bv.z);
            unsigned long long b3 = pack2(bv.w, bv.w);
            fma2(ap[0][0], a01, b0); fma2(ap[1][0], a23, b0);
            fma2(ap[2][0], a45, b0); fma2(ap[3][0], a67, b0);
            fma2(ap[0][1], a01, b1); fma2(ap[1][1], a23, b1);
            fma2(ap[2][1], a45, b1); fma2(ap[3][1], a67, b1);
            fma2(ap[0][2], a01, b2); fma2(ap[1][2], a23, b2);
            fma2(ap[2][2], a45, b2); fma2(ap[3][2], a67, b2);
            fma2(ap[0][3], a01, b3); fma2(ap[1][3], a23, b3);
            fma2(ap[2][3], a45, b3); fma2(ap[3][3], a67, b3);
        }
        __syncthreads();
    }

    // epilogue: add bias, store transposed to g_xpT[t][g][b]
    float bias[4];
    int   gcol[4];
    #pragma unroll
    for (int j = 0; j < 4; j++) {
        int gl = gin0 + tn * 4 + j;
        gcol[j] = gate * 512 + gl;
        bias[j] = bxp[gl] + bhp[gl];
    }
    #pragma unroll
    for (int mp = 0; mp < 4; mp++) {
        int M0 = row0 + tm * 8 + 2 * mp;      // even; pair never crosses a 64-row block
        size_t t0 = (size_t)(M0 >> 6);
        int b0 = M0 & 63;
        #pragma unroll
        for (int j = 0; j < 4; j++) {
            float2 v = unpack2(ap[mp][j]);
            size_t base = (t0 * G4 + gcol[j]) * B_SZ;
            g_xpT[base + b0]     = v.x + bias[j];
            g_xpT[base + b0 + 1] = v.y + bias[j];
        }
    }
}

// =====================================================================
// Phase 2: persistent recurrence. 128 CTAs x 256 threads.
// CTA ct owns units [4ct, 4ct+4) -> 16 gate-rows (r = q*4 + jl).
// ws k-major [512][20-pad], hs k-major [512][72-pad].
// Thread tile: 8 rows x 2 batches, k split 4 ways (shuffle reduce).
// =====================================================================
__global__ __launch_bounds__(256) void lstm_rec(
    const float* __restrict__ Whf, const float* __restrict__ Whi,
    const float* __restrict__ Who, const float* __restrict__ Whg,
    float* __restrict__ out)
{
    extern __shared__ float sm[];
    float* ws  = sm;                                // [512][20]  40 KB
    float* hs  = ws + 512 * WS_STRIDE;              // [512][72]  144 KB
    float* zbT = hs + 512 * HS_STRIDE;              // [64][17]   4.25 KB
    __shared__ unsigned s_base;

    const int ct  = blockIdx.x;
    const int tid = threadIdx.x;
    const int j0  = ct * 4;

    // Load Wh slice transposed: ws[k*20 + r], r = q*4+jl
    for (int idx = tid; idx < 16 * 512; idx += 256) {
        int r = idx >> 9;
        int k = idx & 511;
        int q = r >> 2, jl = r & 3;
        const float* whp = (q == 0) ? Whf : (q == 1) ? Whi : (q == 2) ? Who : Whg;
        ws[k * WS_STRIDE + r] = whp[(size_t)(j0 + jl) * H_SZ + k];
    }
    if (tid == 0) s_base = g_arrive[ct];   // monotonic base (own slot, consistent)
    __syncthreads();
    const unsigned base = s_base;

    // compute mapping
    const int ks = tid & 3;                // k slice: k = 4*kk + ks
    const int bg = (tid >> 2) & 31;        // batch pair b0 = 2*bg
    const int rg = tid >> 7;               // row group: rows 8*rg .. 8*rg+7
    const int b0 = 2 * bg;
    const int r0 = 8 * rg;

    const unsigned ws_u = smem_u32(ws);
    const unsigned hs_u = smem_u32(hs);
    const unsigned zb_u = smem_u32(zbT);
    const unsigned wa0  = ws_u + (unsigned)((ks * WS_STRIDE + r0) * 4);
    const unsigned ha0  = hs_u + (unsigned)((ks * HS_STRIDE + b0) * 4);

    // update mapping: (unit ujl, batch ub)
    const int ujl = tid >> 6;
    const int ub  = tid & 63;
    float c_reg = 0.0f;

    for (int t = 0; t < T_STEPS; t++) {
        // ---- prefetch xp for this step's gate update (independent of h) ----
        float xq0, xq1, xq2, xq3;
        {
            size_t xb = ((size_t)t * G4 + j0 + ujl) * B_SZ + ub;
            xq0 = g_xpT[xb];
            xq1 = g_xpT[xb + (size_t)512 * B_SZ];
            xq2 = g_xpT[xb + (size_t)1024 * B_SZ];
            xq3 = g_xpT[xb + (size_t)1536 * B_SZ];
        }

        unsigned long long acc[8];
        #pragma unroll
        for (int i = 0; i < 8; i++) acc[i] = 0ull;

        if (t > 0) {
            // ---- stage h_{t-1} from g_hT (k-major) in 2 cp.async groups ----
            const float* hsrc = g_hT + (size_t)(t - 1) * H_SZ * B_SZ;
            #pragma unroll
            for (int i = 0; i < 16; i++) {          // group A: k < 256
                int idx = tid + i * 256;
                int k = idx >> 4, b4 = idx & 15;
                cp_async16(hs_u + (unsigned)((k * HS_STRIDE + b4 * 4) * 4),
                           hsrc + (size_t)k * B_SZ + b4 * 4);
            }
            cp_commit();
            #pragma unroll
            for (int i = 16; i < 32; i++) {         // group B: k >= 256
                int idx = tid + i * 256;
                int k = idx >> 4, b4 = idx & 15;
                cp_async16(hs_u + (unsigned)((k * HS_STRIDE + b4 * 4) * 4),
                           hsrc + (size_t)k * B_SZ + b4 * 4);
            }
            cp_commit();

            cp_wait1();
            __syncthreads();
            // ---- compute on k < 256 (kk 0..63) while group B lands ----
            #pragma unroll 4
            for (int kk = 0; kk < 64; kk++) {
                unsigned long long w01, w23, w45, w67;
                unsigned wa = wa0 + (unsigned)(kk * (4 * WS_STRIDE * 4));
                unsigned ha = ha0 + (unsigned)(kk * (4 * HS_STRIDE * 4));
                lds_v2u64(w01, w23, wa);
                lds_v2u64(w45, w67, wa + 16);
                float h0, h1; lds_v2f32(h0, h1, ha);
                unsigned long long h00 = pack2(h0, h0);
                unsigned long long h11 = pack2(h1, h1);
                fma2(acc[0], w01, h00); fma2(acc[1], w23, h00);
                fma2(acc[2], w45, h00); fma2(acc[3], w67, h00);
                fma2(acc[4], w01, h11); fma2(acc[5], w23, h11);
                fma2(acc[6], w45, h11); fma2(acc[7], w67, h11);
            }
            cp_wait0();
            __syncthreads();
            #pragma unroll 4
            for (int kk = 64; kk < 128; kk++) {
                unsigned long long w01, w23, w45, w67;
                unsigned wa = wa0 + (unsigned)(kk * (4 * WS_STRIDE * 4));
                unsigned ha = ha0 + (unsigned)(kk * (4 * HS_STRIDE * 4));
                lds_v2u64(w01, w23, wa);
                lds_v2u64(w45, w67, wa + 16);
                float h0, h1; lds_v2f32(h0, h1, ha);
                unsigned long long h00 = pack2(h0, h0);
                unsigned long long h11 = pack2(h1, h1);
                fma2(acc[0], w01, h00); fma2(acc[1], w23, h00);
                fma2(acc[2], w45, h00); fma2(acc[3], w67, h00);
                fma2(acc[4], w01, h11); fma2(acc[5], w23, h11);
                fma2(acc[6], w45, h11); fma2(acc[7], w67, h11);
            }
        }

        // ---- reduce across the 4 k-slices (lanes ks=0..3 differ in bits 0-1) ----
        #pragma unroll
        for (int i = 0; i < 8; i++) {
            float2 v = unpack2(acc[i]);
            v.x += __shfl_xor_sync(0xffffffffu, v.x, 1);
            v.y += __shfl_xor_sync(0xffffffffu, v.y, 1);
            v.x += __shfl_xor_sync(0xffffffffu, v.x, 2);
            v.y += __shfl_xor_sync(0xffffffffu, v.y, 2);
            acc[i] = pack2(v.x, v.y);
        }
        if (ks == 0) {
            // acc[p]   = rows (r0+2p, r0+2p+1) @ batch b0
            // acc[4+p] = rows (r0+2p, r0+2p+1) @ batch b0+1
            // zbT stride 17 is odd -> odd batch rows are only 4B aligned: scalar stores.
            #pragma unroll
            for (int p = 0; p < 4; p++) {
                float2 v0 = unpack2(acc[p]);
                float2 v1 = unpack2(acc[4 + p]);
                unsigned e0 = zb_u + (unsigned)((b0 * 17 + r0 + 2 * p) * 4);
                unsigned e1 = zb_u + (unsigned)(((b0 + 1) * 17 + r0 + 2 * p) * 4);
                sts_f32(e0,     v0.x);
                sts_f32(e0 + 4, v0.y);
                sts_f32(e1,     v1.x);
                sts_f32(e1 + 4, v1.y);
            }
        }
        __syncthreads();

        // ---- gate update: rows f=jl, i=4+jl, o=8+jl, g=12+jl ----
        {
            float zf = zbT[ub * 17 + 0  + ujl] + xq0;
            float zi = zbT[ub * 17 + 4  + ujl] + xq1;
            float zo = zbT[ub * 17 + 8  + ujl] + xq2;
            float zg = zbT[ub * 17 + 12 + ujl] + xq3;
            float f  = sigf(zf);
            float ii = sigf(zi);
            float o  = sigf(zo);
            float g  = tanh_fast(zg);
            c_reg    = fmaf(f, c_reg, ii * g);
            float h  = o * tanh_fast(c_reg);
            out[((size_t)t * B_SZ + ub) * H_SZ + j0 + ujl] = h;
            g_hT[((size_t)t * H_SZ + j0 + ujl) * B_SZ + ub] = h;
            if (t == T_STEPS - 1) {
                size_t tail = (size_t)T_STEPS * B_SZ * H_SZ;
                out[tail + (size_t)ub * H_SZ + j0 + ujl] = h;
                out[tail + (size_t)B_SZ * H_SZ + (size_t)ub * H_SZ + j0 + ujl] = c_reg;
            }
        }

        grid_barrier(ct, tid, base + (unsigned)t + 1u);
    }
}

// =====================================================================
extern "C" void kernel_launch(void* const* d_in, const int* in_sizes, int n_in,
                              void* d_out, int out_size)
{
    const float* x   = (const float*)d_in[0];
    const float* Wxf = (const float*)d_in[1];  const float* bxf = (const float*)d_in[2];
    const float* Whf = (const float*)d_in[3];  const float* bhf = (const float*)d_in[4];
    const float* Wxi = (const float*)d_in[5];  const float* bxi = (const float*)d_in[6];
    const float* Whi = (const float*)d_in[7];  const float* bhi = (const float*)d_in[8];
    const float* Wxo = (const float*)d_in[9];  const float* bxo = (const float*)d_in[10];
    const float* Who = (const float*)d_in[11]; const float* bho = (const float*)d_in[12];
    const float* Wxg = (const float*)d_in[13]; const float* bxg = (const float*)d_in[14];
    const float* Whg = (const float*)d_in[15]; const float* bhg = (const float*)d_in[16];
    float* out = (float*)d_out;

    dim3 ggrid(G4 / 64, (T_STEPS * B_SZ) / 128);
    xp_gemm<<<ggrid, 256>>>(x, Wxf, Wxi, Wxo, Wxg,
                            bxf, bxi, bxo, bxg,
                            bhf, bhi, bho, bhg);

    const int smem_bytes = (512 * WS_STRIDE + 512 * HS_STRIDE + 64 * 17) * 4;
    cudaFuncSetAttribute(lstm_rec, cudaFuncAttributeMaxDynamicSharedMemorySize, smem_bytes);
    lstm_rec<<<NCTA, 256, smem_bytes>>>(Whf, Whi, Who, Whg, out);
}